// round 5
// baseline (speedup 1.0000x reference)
#include <cuda_runtime.h>
#include <math.h>

// ---------------------------------------------------------------------------
// Problem constants
// ---------------------------------------------------------------------------
constexpr int BATCH  = 16;
constexpr int NPOS   = 784;          // 28*28
constexpr int CDIM   = 512;
constexpr int NHEADS = 16;
constexpr int DHEAD  = 32;
constexpr int FFD    = 2048;
constexpr int NREL   = 1596;
constexpr int MROWS  = BATCH * NPOS; // 12544

constexpr size_t SZ_NC = (size_t)BATCH * NPOS * CDIM;   // 6,422,528 floats
constexpr size_t SZ_FF = (size_t)BATCH * NPOS * FFD;    // 25,690,112 floats

// Scratch: xc, xn, q, k, v, att, x1, x2 (8 * SZ_NC) + h1 (SZ_FF)  ~= 294 MB
__device__ float g_buf[8 * SZ_NC + SZ_FF];

// ---------------------------------------------------------------------------
// Helpers
// ---------------------------------------------------------------------------
__device__ __forceinline__ unsigned long long pack_dup(float x) {
    unsigned long long r;
    unsigned int u = __float_as_uint(x);
    asm("mov.b64 %0, {%1, %2};" : "=l"(r) : "r"(u), "r"(u));
    return r;
}
__device__ __forceinline__ void fma_f32x2(unsigned long long& d,
                                          unsigned long long a,
                                          unsigned long long b) {
    asm("fma.rn.f32x2 %0, %1, %2, %0;" : "+l"(d) : "l"(a), "l"(b));
}
__device__ __forceinline__ float2 unpack_f32x2(unsigned long long v) {
    return make_float2(__uint_as_float((unsigned int)(v & 0xffffffffull)),
                       __uint_as_float((unsigned int)(v >> 32)));
}
__device__ __forceinline__ float gelu_exact(float x) {
    return 0.5f * x * (1.0f + erff(x * 0.7071067811865476f));
}

// ---------------------------------------------------------------------------
// Tiled 2D transpose per batch:  src [R][Cc]  ->  dst [Cc][R]
// ---------------------------------------------------------------------------
__global__ void transpose_kernel(const float* __restrict__ in,
                                 float* __restrict__ out, int R, int Cc) {
    __shared__ float tile[32][33];
    const int b = blockIdx.z;
    const float* src = in  + (size_t)b * R * Cc;
    float*       dst = out + (size_t)b * R * Cc;
    const int c0 = blockIdx.x * 32;
    const int r0 = blockIdx.y * 32;
    const int tx = threadIdx.x, ty = threadIdx.y;

    #pragma unroll
    for (int j = 0; j < 32; j += 8) {
        int r = r0 + ty + j, c = c0 + tx;
        if (r < R && c < Cc) tile[ty + j][tx] = src[(size_t)r * Cc + c];
    }
    __syncthreads();
    #pragma unroll
    for (int j = 0; j < 32; j += 8) {
        int oc = c0 + ty + j;   // output row  = src col
        int orr = r0 + tx;      // output col  = src row
        if (oc < Cc && orr < R) dst[(size_t)oc * R + orr] = tile[tx][ty + j];
    }
}

// ---------------------------------------------------------------------------
// LayerNorm over C=512, one block (128 threads) per (b,n) row
// ---------------------------------------------------------------------------
__global__ void __launch_bounds__(128) ln_kernel(const float* __restrict__ xc,
                                                 const float* __restrict__ w,
                                                 const float* __restrict__ bsh,
                                                 float* __restrict__ xn) {
    const int row = blockIdx.x;
    const int tid = threadIdx.x;
    const float* xr = xc + (size_t)row * CDIM;
    float4 v = *(const float4*)&xr[tid << 2];
    float s  = v.x + v.y + v.z + v.w;
    float ss = v.x * v.x + v.y * v.y + v.z * v.z + v.w * v.w;
    #pragma unroll
    for (int o = 16; o; o >>= 1) {
        s  += __shfl_xor_sync(0xffffffffu, s, o);
        ss += __shfl_xor_sync(0xffffffffu, ss, o);
    }
    __shared__ float rs[4], rss[4];
    const int warp = tid >> 5, lane = tid & 31;
    if (lane == 0) { rs[warp] = s; rss[warp] = ss; }
    __syncthreads();
    if (tid == 0) {
        float S  = rs[0] + rs[1] + rs[2] + rs[3];
        float SS = rss[0] + rss[1] + rss[2] + rss[3];
        float mu  = S * (1.0f / CDIM);
        float var = SS * (1.0f / CDIM) - mu * mu;
        rs[0]  = mu;
        rss[0] = rsqrtf(var + 1e-5f);
    }
    __syncthreads();
    const float mu = rs[0], rstd = rss[0];
    float4 wv = *(const float4*)&w[tid << 2];
    float4 bv = *(const float4*)&bsh[tid << 2];
    float4 o;
    o.x = (v.x - mu) * rstd * wv.x + bv.x;
    o.y = (v.y - mu) * rstd * wv.y + bv.y;
    o.z = (v.z - mu) * rstd * wv.z + bv.z;
    o.w = (v.w - mu) * rstd * wv.w + bv.w;
    *(float4*)&xn[(size_t)row * CDIM + (tid << 2)] = o;
}

// ---------------------------------------------------------------------------
// Generic fp32 GEMM:  C = A[M,K] @ B[K,Nc] + bias   (+ GELU or + residual)
// 128x128 block, BK=8, 256 threads, 8x8 microtile via packed fma.rn.f32x2.
// All dims divide tiles exactly (M=12544, Nc in {512,2048}, K in {512,2048}).
// EPI: 0 = bias, 1 = bias+gelu(exact), 2 = bias+residual
// ---------------------------------------------------------------------------
template <int EPI>
__global__ void __launch_bounds__(256, 2) gemm_kernel(
    const float* __restrict__ A, const float* __restrict__ Bm,
    const float* __restrict__ bias, const float* __restrict__ res,
    float* __restrict__ Cout, int M, int K, int Nc) {
    __shared__ float As[8][128];
    __shared__ float Bs[8][128];
    const int tid  = threadIdx.x;
    const int row0 = blockIdx.y * 128;
    const int col0 = blockIdx.x * 128;
    const int am  = tid >> 1;            // 0..127
    const int ak  = (tid & 1) << 2;      // 0 or 4
    const int bkr = tid >> 5;            // 0..7
    const int bc  = (tid & 31) << 2;     // 0..124
    const int wr  = (tid >> 4) << 3;     // 0..120
    const int wc  = (tid & 15) << 3;     // 0..120

    unsigned long long acc[8][4];
    #pragma unroll
    for (int i = 0; i < 8; ++i)
        #pragma unroll
        for (int j = 0; j < 4; ++j) acc[i][j] = 0ull;

    float4 av = *(const float4*)&A[(size_t)(row0 + am) * K + ak];
    float4 bv = *(const float4*)&Bm[(size_t)bkr * Nc + col0 + bc];

    for (int k0 = 0; k0 < K; k0 += 8) {
        As[ak + 0][am] = av.x;
        As[ak + 1][am] = av.y;
        As[ak + 2][am] = av.z;
        As[ak + 3][am] = av.w;
        *(float4*)&Bs[bkr][bc] = bv;
        __syncthreads();
        if (k0 + 8 < K) {
            av = *(const float4*)&A[(size_t)(row0 + am) * K + (k0 + 8) + ak];
            bv = *(const float4*)&Bm[(size_t)(k0 + 8 + bkr) * Nc + col0 + bc];
        }
        #pragma unroll
        for (int kk = 0; kk < 8; ++kk) {
            float a[8];
            *(float4*)&a[0] = *(const float4*)&As[kk][wr];
            *(float4*)&a[4] = *(const float4*)&As[kk][wr + 4];
            unsigned long long b2[4];
            ulonglong2 t0 = *(const ulonglong2*)&Bs[kk][wc];
            ulonglong2 t1 = *(const ulonglong2*)&Bs[kk][wc + 4];
            b2[0] = t0.x; b2[1] = t0.y; b2[2] = t1.x; b2[3] = t1.y;
            #pragma unroll
            for (int i = 0; i < 8; ++i) {
                unsigned long long a2 = pack_dup(a[i]);
                #pragma unroll
                for (int j = 0; j < 4; ++j) fma_f32x2(acc[i][j], a2, b2[j]);
            }
        }
        __syncthreads();
    }

    #pragma unroll
    for (int i = 0; i < 8; ++i) {
        const size_t r = (size_t)(row0 + wr + i);
        #pragma unroll
        for (int jp = 0; jp < 4; ++jp) {
            const int c = col0 + wc + jp * 2;
            float2 cv = unpack_f32x2(acc[i][jp]);
            float v0 = cv.x + bias[c];
            float v1 = cv.y + bias[c + 1];
            if (EPI == 1) { v0 = gelu_exact(v0); v1 = gelu_exact(v1); }
            if (EPI == 2) { v0 += res[r * Nc + c]; v1 += res[r * Nc + c + 1]; }
            *(float2*)&Cout[r * Nc + c] = make_float2(v0, v1);
        }
    }
}

// ---------------------------------------------------------------------------
// Fused attention for one (b, h, 16-query tile).
// Exact two-pass softmax with the full 784-wide score rows in smem.
// q/k/v are [b][n][c] with c = h*32 + d. No 1/sqrt(d) scale (matches ref).
// smem: sS[16][784] + sQ[16][33] + sKV[112][33]  = 67072 bytes (dynamic)
// ---------------------------------------------------------------------------
constexpr int ATTN_SMEM = (16 * 784 + 16 * 33 + 112 * 33) * 4;

__global__ void __launch_bounds__(256) attn_kernel(
    const float* __restrict__ q, const float* __restrict__ k,
    const float* __restrict__ v, const float* __restrict__ rel_bias,
    const int* __restrict__ rel_idx, float* __restrict__ att) {
    const int qt = blockIdx.x;   // 0..48
    const int h  = blockIdx.y;   // 0..15
    const int b  = blockIdx.z;   // 0..15
    const int n0 = qt * 16;
    const int tid = threadIdx.x;

    extern __shared__ float sm[];
    float* sS  = sm;                 // 16 x 784
    float* sQ  = sm + 16 * 784;      // 16 x 33 (padded)
    float* sKV = sQ + 16 * 33;       // 112 x 33 (padded)

    // load Q tile
    #pragma unroll
    for (int e = tid; e < 16 * 32; e += 256) {
        int qi = e >> 5, d = e & 31;
        sQ[qi * 33 + d] = q[((size_t)(b * NPOS + n0 + qi)) * CDIM + h * DHEAD + d];
    }

    // ---- pass 1: scores = q.k^T + bias ----
    for (int kt = 0; kt < 7; ++kt) {
        const int m0 = kt * 112;
        __syncthreads();
        #pragma unroll
        for (int e = tid; e < 112 * 32; e += 256) {
            int mi = e >> 5, d = e & 31;
            sKV[mi * 33 + d] =
                k[((size_t)(b * NPOS + m0 + mi)) * CDIM + h * DHEAD + d];
        }
        __syncthreads();
        #pragma unroll
        for (int p = tid; p < 16 * 112; p += 256) {
            int qi = p / 112, mi = p % 112;
            const float* qr = &sQ[qi * 33];
            const float* kr = &sKV[mi * 33];
            float s = 0.0f;
            #pragma unroll
            for (int d = 0; d < 32; ++d) s += qr[d] * kr[d];
            const int m  = m0 + mi;
            const int rl = rel_idx[(size_t)(n0 + qi) * NPOS + m];
            s += rel_bias[h * NREL + rl];
            sS[qi * 784 + m] = s;
        }
    }
    __syncthreads();

    // ---- pass 2: softmax per query row (warp handles rows w and w+8) ----
    {
        const int warp = tid >> 5, lane = tid & 31;
        #pragma unroll
        for (int rr = 0; rr < 2; ++rr) {
            float* row = sS + (warp + rr * 8) * 784;
            float mx = -1e30f;
            for (int m = lane; m < 784; m += 32) mx = fmaxf(mx, row[m]);
            #pragma unroll
            for (int o = 16; o; o >>= 1)
                mx = fmaxf(mx, __shfl_xor_sync(0xffffffffu, mx, o));
            float sum = 0.0f;
            for (int m = lane; m < 784; m += 32) {
                float e = expf(row[m] - mx);
                row[m] = e;
                sum += e;
            }
            #pragma unroll
            for (int o = 16; o; o >>= 1)
                sum += __shfl_xor_sync(0xffffffffu, sum, o);
            const float inv = 1.0f / sum;
            for (int m = lane; m < 784; m += 32) row[m] *= inv;
        }
    }

    // ---- pass 3: out = attn @ v ----
    const int qi0 = tid >> 5;   // 0..7 (also handles qi0+8)
    const int d   = tid & 31;
    float acc0 = 0.0f, acc1 = 0.0f;
    for (int kt = 0; kt < 7; ++kt) {
        const int m0 = kt * 112;
        __syncthreads();
        #pragma unroll
        for (int e = tid; e < 112 * 32; e += 256) {
            int mi = e >> 5, dd = e & 31;
            sKV[mi * 33 + dd] =
                v[((size_t)(b * NPOS + m0 + mi)) * CDIM + h * DHEAD + dd];
        }
        __syncthreads();
        #pragma unroll 4
        for (int mi = 0; mi < 112; ++mi) {
            const float vv = sKV[mi * 33 + d];
            acc0 = fmaf(sS[qi0 * 784 + m0 + mi], vv, acc0);
            acc1 = fmaf(sS[(qi0 + 8) * 784 + m0 + mi], vv, acc1);
        }
    }
    att[((size_t)(b * NPOS + n0 + qi0)) * CDIM + h * DHEAD + d] = acc0;
    att[((size_t)(b * NPOS + n0 + qi0 + 8)) * CDIM + h * DHEAD + d] = acc1;
}

// ---------------------------------------------------------------------------
// Launch
// ---------------------------------------------------------------------------
extern "C" void kernel_launch(void* const* d_in, const int* in_sizes, int n_in,
                              void* d_out, int out_size) {
    (void)in_sizes; (void)n_in; (void)out_size;
    const float* x      = (const float*)d_in[0];
    const float* ln_w   = (const float*)d_in[1];
    const float* ln_b   = (const float*)d_in[2];
    const float* Wq     = (const float*)d_in[3];
    const float* bq     = (const float*)d_in[4];
    const float* Wk     = (const float*)d_in[5];
    const float* bk     = (const float*)d_in[6];
    const float* Wv     = (const float*)d_in[7];
    const float* bv     = (const float*)d_in[8];
    const float* Wo     = (const float*)d_in[9];
    const float* bo     = (const float*)d_in[10];
    const float* relb   = (const float*)d_in[11];
    const float* W1     = (const float*)d_in[12];
    const float* b1     = (const float*)d_in[13];
    const float* W2     = (const float*)d_in[14];
    const float* b2     = (const float*)d_in[15];
    const int*   relidx = (const int*)d_in[16];
    float* out = (float*)d_out;

    float* buf = nullptr;
    cudaGetSymbolAddress((void**)&buf, g_buf);
    float* xc  = buf + 0 * SZ_NC;
    float* xn  = buf + 1 * SZ_NC;
    float* qb  = buf + 2 * SZ_NC;
    float* kb  = buf + 3 * SZ_NC;
    float* vb  = buf + 4 * SZ_NC;
    float* att = buf + 5 * SZ_NC;
    float* x1  = buf + 6 * SZ_NC;
    float* x2  = buf + 7 * SZ_NC;
    float* h1  = buf + 8 * SZ_NC;

    cudaFuncSetAttribute(attn_kernel,
                         cudaFuncAttributeMaxDynamicSharedMemorySize,
                         ATTN_SMEM);

    const dim3 tb(32, 8);
    // NCHW -> (b, n, c)
    transpose_kernel<<<dim3(25, 16, BATCH), tb>>>(x, xc, CDIM, NPOS);
    // LayerNorm
    ln_kernel<<<MROWS, 128>>>(xc, ln_w, ln_b, xn);
    // Q / K / V projections
    const dim3 g512(CDIM / 128, MROWS / 128);   // (4, 98)
    const dim3 g2048(FFD / 128, MROWS / 128);   // (16, 98)
    gemm_kernel<0><<<g512, 256>>>(xn, Wq, bq, nullptr, qb, MROWS, CDIM, CDIM);
    gemm_kernel<0><<<g512, 256>>>(xn, Wk, bk, nullptr, kb, MROWS, CDIM, CDIM);
    gemm_kernel<0><<<g512, 256>>>(xn, Wv, bv, nullptr, vb, MROWS, CDIM, CDIM);
    // Attention
    attn_kernel<<<dim3(49, NHEADS, BATCH), 256, ATTN_SMEM>>>(qb, kb, vb, relb,
                                                             relidx, att);
    // x1 = xc + att @ Wo + bo
    gemm_kernel<2><<<g512, 256>>>(att, Wo, bo, xc, x1, MROWS, CDIM, CDIM);
    // h1 = gelu(x1 @ W1 + b1)
    gemm_kernel<1><<<g2048, 256>>>(x1, W1, b1, nullptr, h1, MROWS, CDIM, FFD);
    // x2 = x1 + h1 @ W2 + b2
    gemm_kernel<2><<<g512, 256>>>(h1, W2, b2, x1, x2, MROWS, FFD, CDIM);
    // (b, n, c) -> NCHW
    transpose_kernel<<<dim3(16, 25, BATCH), tb>>>(x2, out, NPOS, CDIM);
}

// round 6
// speedup vs baseline: 1.2073x; 1.2073x over previous
#include <cuda_runtime.h>
#include <math.h>

// ---------------------------------------------------------------------------
// Problem constants
// ---------------------------------------------------------------------------
constexpr int BATCH  = 16;
constexpr int NPOS   = 784;          // 28*28
constexpr int CDIM   = 512;
constexpr int NHEADS = 16;
constexpr int DHEAD  = 32;
constexpr int FFD    = 2048;
constexpr int NREL   = 1596;
constexpr int MROWS  = BATCH * NPOS; // 12544

constexpr size_t SZ_NC = (size_t)BATCH * NPOS * CDIM;
constexpr size_t SZ_FF = (size_t)BATCH * NPOS * FFD;

__device__ float g_buf[8 * SZ_NC + SZ_FF];

// ---------------------------------------------------------------------------
// Helpers
// ---------------------------------------------------------------------------
__device__ __forceinline__ void fma_f32x2(unsigned long long& d,
                                          unsigned long long a,
                                          unsigned long long b) {
    asm("fma.rn.f32x2 %0, %1, %2, %0;" : "+l"(d) : "l"(a), "l"(b));
}
__device__ __forceinline__ float2 unpack_f32x2(unsigned long long v) {
    return make_float2(__uint_as_float((unsigned int)(v & 0xffffffffull)),
                       __uint_as_float((unsigned int)(v >> 32)));
}
__device__ __forceinline__ float gelu_exact(float x) {
    return 0.5f * x * (1.0f + erff(x * 0.7071067811865476f));
}

// ---------------------------------------------------------------------------
// Tiled 2D transpose per batch:  src [R][Cc]  ->  dst [Cc][R]
// ---------------------------------------------------------------------------
__global__ void transpose_kernel(const float* __restrict__ in,
                                 float* __restrict__ out, int R, int Cc) {
    __shared__ float tile[32][33];
    const int b = blockIdx.z;
    const float* src = in  + (size_t)b * R * Cc;
    float*       dst = out + (size_t)b * R * Cc;
    const int c0 = blockIdx.x * 32;
    const int r0 = blockIdx.y * 32;
    const int tx = threadIdx.x, ty = threadIdx.y;

    #pragma unroll
    for (int j = 0; j < 32; j += 8) {
        int r = r0 + ty + j, c = c0 + tx;
        if (r < R && c < Cc) tile[ty + j][tx] = src[(size_t)r * Cc + c];
    }
    __syncthreads();
    #pragma unroll
    for (int j = 0; j < 32; j += 8) {
        int oc = c0 + ty + j;
        int orr = r0 + tx;
        if (oc < Cc && orr < R) dst[(size_t)oc * R + orr] = tile[tx][ty + j];
    }
}

// ---------------------------------------------------------------------------
// LayerNorm over C=512, one block (128 threads) per (b,n) row
// ---------------------------------------------------------------------------
__global__ void __launch_bounds__(128) ln_kernel(const float* __restrict__ xc,
                                                 const float* __restrict__ w,
                                                 const float* __restrict__ bsh,
                                                 float* __restrict__ xn) {
    const int row = blockIdx.x;
    const int tid = threadIdx.x;
    const float* xr = xc + (size_t)row * CDIM;
    float4 v = *(const float4*)&xr[tid << 2];
    float s  = v.x + v.y + v.z + v.w;
    float ss = v.x * v.x + v.y * v.y + v.z * v.z + v.w * v.w;
    #pragma unroll
    for (int o = 16; o; o >>= 1) {
        s  += __shfl_xor_sync(0xffffffffu, s, o);
        ss += __shfl_xor_sync(0xffffffffu, ss, o);
    }
    __shared__ float rs[4], rss[4];
    const int warp = tid >> 5, lane = tid & 31;
    if (lane == 0) { rs[warp] = s; rss[warp] = ss; }
    __syncthreads();
    if (tid == 0) {
        float S  = rs[0] + rs[1] + rs[2] + rs[3];
        float SS = rss[0] + rss[1] + rss[2] + rss[3];
        float mu  = S * (1.0f / CDIM);
        float var = SS * (1.0f / CDIM) - mu * mu;
        rs[0]  = mu;
        rss[0] = rsqrtf(var + 1e-5f);
    }
    __syncthreads();
    const float mu = rs[0], rstd = rss[0];
    float4 wv = *(const float4*)&w[tid << 2];
    float4 bv = *(const float4*)&bsh[tid << 2];
    float4 o;
    o.x = (v.x - mu) * rstd * wv.x + bv.x;
    o.y = (v.y - mu) * rstd * wv.y + bv.y;
    o.z = (v.z - mu) * rstd * wv.z + bv.z;
    o.w = (v.w - mu) * rstd * wv.w + bv.w;
    *(float4*)&xn[(size_t)row * CDIM + (tid << 2)] = o;
}

// ---------------------------------------------------------------------------
// fp32 GEMM, 128x128 tile, BK=8, 256 threads, 8x8 microtile, f32x2 FMAs.
// A stored duplicated in smem ({a,a} pairs -> no pack MOVs); B fragment split
// into two 16B chunks 64 cols apart (conflict-free LDS.128); double-buffered
// smem (1 sync per k-step).
// EPI: 0 = bias, 1 = bias+gelu(exact), 2 = bias+residual
// ---------------------------------------------------------------------------
template <int EPI>
__global__ void __launch_bounds__(256, 2) gemm_kernel(
    const float* __restrict__ A, const float* __restrict__ Bm,
    const float* __restrict__ bias, const float* __restrict__ res,
    float* __restrict__ Cout, int M, int K, int Nc) {
    __shared__ float Asd[2][8][256];   // duplicated: col 2m,2m+1 hold A[m]
    __shared__ float Bs[2][8][128];

    const int tid  = threadIdx.x;
    const int row0 = blockIdx.y * 128;
    const int col0 = blockIdx.x * 128;

    const int am  = tid & 127;           // A row within tile
    const int ak  = (tid >> 7) << 2;     // 0 or 4 (k offset)
    const int bkr = tid >> 5;            // 0..7  (B k row)
    const int bc  = (tid & 31) << 2;     // 0..124
    const int wr  = (tid >> 4) << 3;     // 0..120 (8 C rows)
    const int wc  = (tid & 15) << 2;     // chunk0 cols; chunk1 at +64

    const float* Aptr = A  + (size_t)(row0 + am) * K + ak;
    const float* Bptr = Bm + (size_t)bkr * Nc + col0 + bc;

    unsigned long long acc[8][4] = {};

    float4 av = *(const float4*)Aptr;
    float4 bv = *(const float4*)Bptr;

    // stage 0
    *(float2*)&Asd[0][ak + 0][2 * am] = make_float2(av.x, av.x);
    *(float2*)&Asd[0][ak + 1][2 * am] = make_float2(av.y, av.y);
    *(float2*)&Asd[0][ak + 2][2 * am] = make_float2(av.z, av.z);
    *(float2*)&Asd[0][ak + 3][2 * am] = make_float2(av.w, av.w);
    *(float4*)&Bs[0][bkr][bc] = bv;
    __syncthreads();

    int buf = 0;
    for (int k0 = 0; k0 < K; k0 += 8) {
        const bool more = (k0 + 8) < K;
        if (more) {
            av = *(const float4*)(Aptr + (k0 + 8));
            bv = *(const float4*)(Bptr + (size_t)(k0 + 8) * Nc);
        }
        #pragma unroll
        for (int kk = 0; kk < 8; ++kk) {
            ulonglong2 a01 = *(const ulonglong2*)&Asd[buf][kk][2 * wr];
            ulonglong2 a23 = *(const ulonglong2*)&Asd[buf][kk][2 * wr + 4];
            ulonglong2 a45 = *(const ulonglong2*)&Asd[buf][kk][2 * wr + 8];
            ulonglong2 a67 = *(const ulonglong2*)&Asd[buf][kk][2 * wr + 12];
            ulonglong2 bA  = *(const ulonglong2*)&Bs[buf][kk][wc];
            ulonglong2 bB  = *(const ulonglong2*)&Bs[buf][kk][wc + 64];
            unsigned long long a2[8] = {a01.x, a01.y, a23.x, a23.y,
                                        a45.x, a45.y, a67.x, a67.y};
            unsigned long long b2[4] = {bA.x, bA.y, bB.x, bB.y};
            #pragma unroll
            for (int i = 0; i < 8; ++i) {
                #pragma unroll
                for (int j = 0; j < 4; ++j) fma_f32x2(acc[i][j], a2[i], b2[j]);
            }
        }
        if (more) {
            const int nb = buf ^ 1;
            *(float2*)&Asd[nb][ak + 0][2 * am] = make_float2(av.x, av.x);
            *(float2*)&Asd[nb][ak + 1][2 * am] = make_float2(av.y, av.y);
            *(float2*)&Asd[nb][ak + 2][2 * am] = make_float2(av.z, av.z);
            *(float2*)&Asd[nb][ak + 3][2 * am] = make_float2(av.w, av.w);
            *(float4*)&Bs[nb][bkr][bc] = bv;
            __syncthreads();
            buf = nb;
        }
    }

    const int cA = col0 + wc;
    const int cB = cA + 64;
    const float4 biasA = *(const float4*)&bias[cA];
    const float4 biasB = *(const float4*)&bias[cB];
    #pragma unroll
    for (int i = 0; i < 8; ++i) {
        const size_t r = (size_t)(row0 + wr + i);
        float2 p0 = unpack_f32x2(acc[i][0]);
        float2 p1 = unpack_f32x2(acc[i][1]);
        float2 p2 = unpack_f32x2(acc[i][2]);
        float2 p3 = unpack_f32x2(acc[i][3]);
        float4 oA = make_float4(p0.x + biasA.x, p0.y + biasA.y,
                                p1.x + biasA.z, p1.y + biasA.w);
        float4 oB = make_float4(p2.x + biasB.x, p2.y + biasB.y,
                                p3.x + biasB.z, p3.y + biasB.w);
        if (EPI == 1) {
            oA.x = gelu_exact(oA.x); oA.y = gelu_exact(oA.y);
            oA.z = gelu_exact(oA.z); oA.w = gelu_exact(oA.w);
            oB.x = gelu_exact(oB.x); oB.y = gelu_exact(oB.y);
            oB.z = gelu_exact(oB.z); oB.w = gelu_exact(oB.w);
        }
        if (EPI == 2) {
            float4 rA = *(const float4*)&res[r * Nc + cA];
            float4 rB = *(const float4*)&res[r * Nc + cB];
            oA.x += rA.x; oA.y += rA.y; oA.z += rA.z; oA.w += rA.w;
            oB.x += rB.x; oB.y += rB.y; oB.z += rB.z; oB.w += rB.w;
        }
        *(float4*)&Cout[r * Nc + cA] = oA;
        *(float4*)&Cout[r * Nc + cB] = oB;
    }
}

// ---------------------------------------------------------------------------
// Fused attention for one (b, h, 16-query tile). Exact two-pass softmax,
// full 784-wide score rows in smem.
//   pass1: 2q x 4m register tile per thread, float4 smem loads
//   pass3: transposed V tile (pad 116), broadcast float4 weight loads
// smem: sS[16][784] + sQ[16][36] + union(sK[112][36], sV[32][116])
// ---------------------------------------------------------------------------
constexpr int SQ_PAD = 36;
constexpr int SK_PAD = 36;
constexpr int SV_PAD = 116;
constexpr int ATTN_SMEM =
    (16 * 784 + 16 * SQ_PAD + 112 * SK_PAD) * 4;  // 112*36=4032 >= 32*116=3712

__global__ void __launch_bounds__(256) attn_kernel(
    const float* __restrict__ q, const float* __restrict__ k,
    const float* __restrict__ v, const float* __restrict__ rel_bias,
    const int* __restrict__ rel_idx, float* __restrict__ att) {
    const int qt = blockIdx.x;   // 0..48
    const int h  = blockIdx.y;
    const int b  = blockIdx.z;
    const int n0 = qt * 16;
    const int tid = threadIdx.x;

    extern __shared__ float sm[];
    float* sS  = sm;                      // 16 x 784
    float* sQ  = sm + 16 * 784;           // 16 x 36
    float* sKV = sQ + 16 * SQ_PAD;        // union: K tile / V tile (transposed)

    // load Q tile
    #pragma unroll
    for (int e = tid; e < 16 * 32; e += 256) {
        int qi = e >> 5, d = e & 31;
        sQ[qi * SQ_PAD + d] =
            q[((size_t)(b * NPOS + n0 + qi)) * CDIM + h * DHEAD + d];
    }

    const int qg  = tid / 28;          // 0..7 (+ garbage for tid>=224)
    const int mg  = tid % 28;          // 0..27
    const int qi0 = qg * 2;
    const bool active = (tid < 224);

    // ---- pass 1: scores = q.k^T + rel_bias ----
    for (int kt = 0; kt < 7; ++kt) {
        const int m0 = kt * 112;
        __syncthreads();
        #pragma unroll
        for (int e = tid; e < 112 * 32; e += 256) {
            int mi = e >> 5, d = e & 31;
            sKV[mi * SK_PAD + d] =
                k[((size_t)(b * NPOS + m0 + mi)) * CDIM + h * DHEAD + d];
        }
        __syncthreads();
        if (active) {
            float acc[2][4] = {};
            #pragma unroll
            for (int d4 = 0; d4 < 32; d4 += 4) {
                float4 q0v = *(const float4*)&sQ[qi0 * SQ_PAD + d4];
                float4 q1v = *(const float4*)&sQ[(qi0 + 1) * SQ_PAD + d4];
                #pragma unroll
                for (int j = 0; j < 4; ++j) {
                    float4 kv = *(const float4*)&sKV[(mg + 28 * j) * SK_PAD + d4];
                    acc[0][j] = fmaf(q0v.x, kv.x, acc[0][j]);
                    acc[0][j] = fmaf(q0v.y, kv.y, acc[0][j]);
                    acc[0][j] = fmaf(q0v.z, kv.z, acc[0][j]);
                    acc[0][j] = fmaf(q0v.w, kv.w, acc[0][j]);
                    acc[1][j] = fmaf(q1v.x, kv.x, acc[1][j]);
                    acc[1][j] = fmaf(q1v.y, kv.y, acc[1][j]);
                    acc[1][j] = fmaf(q1v.z, kv.z, acc[1][j]);
                    acc[1][j] = fmaf(q1v.w, kv.w, acc[1][j]);
                }
            }
            int   rl[2][4];
            #pragma unroll
            for (int r = 0; r < 2; ++r)
                #pragma unroll
                for (int j = 0; j < 4; ++j)
                    rl[r][j] = rel_idx[(size_t)(n0 + qi0 + r) * NPOS +
                                       (m0 + mg + 28 * j)];
            #pragma unroll
            for (int r = 0; r < 2; ++r)
                #pragma unroll
                for (int j = 0; j < 4; ++j) {
                    const int m = m0 + mg + 28 * j;
                    sS[(qi0 + r) * 784 + m] =
                        acc[r][j] + rel_bias[h * NREL + rl[r][j]];
                }
        }
    }
    __syncthreads();

    // ---- pass 2: softmax per query row (warp w handles rows w, w+8) ----
    {
        const int warp = tid >> 5, lane = tid & 31;
        #pragma unroll
        for (int rr = 0; rr < 2; ++rr) {
            float* row = sS + (warp + rr * 8) * 784;
            float mx = -1e30f;
            for (int m = lane; m < 784; m += 32) mx = fmaxf(mx, row[m]);
            #pragma unroll
            for (int o = 16; o; o >>= 1)
                mx = fmaxf(mx, __shfl_xor_sync(0xffffffffu, mx, o));
            float sum = 0.0f;
            for (int m = lane; m < 784; m += 32) {
                float e = expf(row[m] - mx);
                row[m] = e;
                sum += e;
            }
            #pragma unroll
            for (int o = 16; o; o >>= 1)
                sum += __shfl_xor_sync(0xffffffffu, sum, o);
            const float inv = 1.0f / sum;
            for (int m = lane; m < 784; m += 32) row[m] *= inv;
        }
    }

    // ---- pass 3: out = attn @ v  (V transposed in smem) ----
    const int warp = tid >> 5;   // row pair {warp, warp+8}
    const int d    = tid & 31;
    float acc0 = 0.0f, acc1 = 0.0f;
    for (int kt = 0; kt < 7; ++kt) {
        const int m0 = kt * 112;
        __syncthreads();
        #pragma unroll
        for (int e = tid; e < 112 * 32; e += 256) {
            int mi = e >> 5, dd = e & 31;
            sKV[dd * SV_PAD + mi] =
                v[((size_t)(b * NPOS + m0 + mi)) * CDIM + h * DHEAD + dd];
        }
        __syncthreads();
        const float* w0 = &sS[warp * 784 + m0];
        const float* w1 = &sS[(warp + 8) * 784 + m0];
        const float* vr = &sKV[d * SV_PAD];
        #pragma unroll 7
        for (int mi = 0; mi < 112; mi += 4) {
            float4 a0 = *(const float4*)&w0[mi];   // broadcast
            float4 a1 = *(const float4*)&w1[mi];   // broadcast
            float4 vv = *(const float4*)&vr[mi];
            acc0 = fmaf(a0.x, vv.x, acc0);
            acc0 = fmaf(a0.y, vv.y, acc0);
            acc0 = fmaf(a0.z, vv.z, acc0);
            acc0 = fmaf(a0.w, vv.w, acc0);
            acc1 = fmaf(a1.x, vv.x, acc1);
            acc1 = fmaf(a1.y, vv.y, acc1);
            acc1 = fmaf(a1.z, vv.z, acc1);
            acc1 = fmaf(a1.w, vv.w, acc1);
        }
    }
    att[((size_t)(b * NPOS + n0 + warp)) * CDIM + h * DHEAD + d]     = acc0;
    att[((size_t)(b * NPOS + n0 + warp + 8)) * CDIM + h * DHEAD + d] = acc1;
}

// ---------------------------------------------------------------------------
// Launch
// ---------------------------------------------------------------------------
extern "C" void kernel_launch(void* const* d_in, const int* in_sizes, int n_in,
                              void* d_out, int out_size) {
    (void)in_sizes; (void)n_in; (void)out_size;
    const float* x      = (const float*)d_in[0];
    const float* ln_w   = (const float*)d_in[1];
    const float* ln_b   = (const float*)d_in[2];
    const float* Wq     = (const float*)d_in[3];
    const float* bq     = (const float*)d_in[4];
    const float* Wk     = (const float*)d_in[5];
    const float* bk     = (const float*)d_in[6];
    const float* Wv     = (const float*)d_in[7];
    const float* bv     = (const float*)d_in[8];
    const float* Wo     = (const float*)d_in[9];
    const float* bo     = (const float*)d_in[10];
    const float* relb   = (const float*)d_in[11];
    const float* W1     = (const float*)d_in[12];
    const float* b1     = (const float*)d_in[13];
    const float* W2     = (const float*)d_in[14];
    const float* b2     = (const float*)d_in[15];
    const int*   relidx = (const int*)d_in[16];
    float* out = (float*)d_out;

    float* buf = nullptr;
    cudaGetSymbolAddress((void**)&buf, g_buf);
    float* xc  = buf + 0 * SZ_NC;
    float* xn  = buf + 1 * SZ_NC;
    float* qb  = buf + 2 * SZ_NC;
    float* kb  = buf + 3 * SZ_NC;
    float* vb  = buf + 4 * SZ_NC;
    float* att = buf + 5 * SZ_NC;
    float* x1  = buf + 6 * SZ_NC;
    float* x2  = buf + 7 * SZ_NC;
    float* h1  = buf + 8 * SZ_NC;

    cudaFuncSetAttribute(attn_kernel,
                         cudaFuncAttributeMaxDynamicSharedMemorySize,
                         ATTN_SMEM);

    const dim3 tb(32, 8);
    transpose_kernel<<<dim3(25, 16, BATCH), tb>>>(x, xc, CDIM, NPOS);
    ln_kernel<<<MROWS, 128>>>(xc, ln_w, ln_b, xn);

    const dim3 g512(CDIM / 128, MROWS / 128);   // (4, 98)
    const dim3 g2048(FFD / 128, MROWS / 128);   // (16, 98)
    gemm_kernel<0><<<g512, 256>>>(xn, Wq, bq, nullptr, qb, MROWS, CDIM, CDIM);
    gemm_kernel<0><<<g512, 256>>>(xn, Wk, bk, nullptr, kb, MROWS, CDIM, CDIM);
    gemm_kernel<0><<<g512, 256>>>(xn, Wv, bv, nullptr, vb, MROWS, CDIM, CDIM);

    attn_kernel<<<dim3(49, NHEADS, BATCH), 256, ATTN_SMEM>>>(qb, kb, vb, relb,
                                                             relidx, att);

    gemm_kernel<2><<<g512, 256>>>(att, Wo, bo, xc, x1, MROWS, CDIM, CDIM);
    gemm_kernel<1><<<g2048, 256>>>(x1, W1, b1, nullptr, h1, MROWS, CDIM, FFD);
    gemm_kernel<2><<<g512, 256>>>(h1, W2, b2, x1, x2, MROWS, FFD, CDIM);

    transpose_kernel<<<dim3(16, 25, BATCH), tb>>>(x2, out, NPOS, CDIM);
}